// round 6
// baseline (speedup 1.0000x reference)
#include <cuda_runtime.h>
#include <math.h>

#define B_   8
#define CIN  128
#define CK   64
#define CV   64
#define CO   128
#define N_   4096
#define KVCHUNKS 32

// ---------------- scratch ----------------
__device__ float g_yq[B_ * CK * N_];      // raw conv(q)+bias
__device__ float g_yk[B_ * CK * N_];      // raw conv(k)+bias
__device__ float g_yv[B_ * CV * N_];      // conv(v)+bias
__device__ float g_WkT[CIN * CK];
__device__ float g_WvT[CIN * CV];
__device__ float g_scale[2 * CK];
__device__ float g_shift[2 * CK];
__device__ float g_rn[2 * B_ * N_];       // per-column 1/(||.||+eps): [which][b][n]
__device__ float g_spart[2 * 64 * 512];   // [which*64+c][b*64+nblk]
__device__ float g_sspart[2 * 64 * 512];
__device__ float g_vpart[512 * 64];       // [b*64+cv][nblk]
__device__ float g_vsum[B_ * CV];
__device__ float g_kvpart[KVCHUNKS * B_ * CK * CV];
__device__ float g_M[B_ * CK * CO];
__device__ float g_obias[B_ * CO];

// ---------------- K0: transpose weights ----------------
__global__ void prep_kernel(const float* __restrict__ Wk, const float* __restrict__ Wv) {
    int idx = blockIdx.x * 256 + threadIdx.x;
    int which = idx >> 13;
    int r = idx & 8191;
    int ci = r >> 6, co = r & 63;
    float v = which ? Wv[co * CIN + ci] : Wk[co * CIN + ci];
    if (which) g_WvT[ci * 64 + co] = v;
    else       g_WkT[ci * 64 + co] = v;
}

// ---------------- K1: 1x1 conv, 64co x 64n tile, scalar 4x4, fused stats ----
// grid (64, B_, 3), 256 threads. z: 0=q, 1=k, 2=v.
__global__ __launch_bounds__(256) void conv_kernel(
    const float* __restrict__ xq, const float* __restrict__ xk,
    const float* __restrict__ xv,
    const float* __restrict__ bk, const float* __restrict__ bv)
{
    int which = blockIdx.z;
    const float* x    = (which == 0) ? xq : (which == 1) ? xk : xv;
    const float* WT   = (which == 2) ? g_WvT : g_WkT;
    const float* bias = (which == 2) ? bv : bk;
    float* y          = (which == 0) ? g_yq : (which == 1) ? g_yk : g_yv;

    int b  = blockIdx.y;
    int n0 = blockIdx.x * 64;
    int tid = threadIdx.x;
    int ty = tid >> 4, tx = tid & 15;

    __shared__ float Ws[64 * 64];   // [ci][co] 16KB
    __shared__ float Xs[64 * 64];   // [ci][n]  16KB

    float acc[4][4] = {};

    for (int s = 0; s < 2; s++) {
        #pragma unroll
        for (int i = 0; i < 4; i++) {
            int e = tid + i * 256;               // float4 index
            int row = e >> 4, col = (e & 15) * 4;
            *(float4*)&Ws[row * 64 + col] =
                *(const float4*)&WT[(s * 64 + row) * 64 + col];
            *(float4*)&Xs[row * 64 + col] =
                *(const float4*)&x[((size_t)(b * CIN + s * 64 + row)) * N_ + n0 + col];
        }
        __syncthreads();
        #pragma unroll 16
        for (int ci = 0; ci < 64; ci++) {
            float4 a = *(const float4*)&Ws[ci * 64 + ty * 4];
            float4 q = *(const float4*)&Xs[ci * 64 + tx * 4];
            acc[0][0] += a.x * q.x; acc[0][1] += a.x * q.y; acc[0][2] += a.x * q.z; acc[0][3] += a.x * q.w;
            acc[1][0] += a.y * q.x; acc[1][1] += a.y * q.y; acc[1][2] += a.y * q.z; acc[1][3] += a.y * q.w;
            acc[2][0] += a.z * q.x; acc[2][1] += a.z * q.y; acc[2][2] += a.z * q.z; acc[2][3] += a.z * q.w;
            acc[3][0] += a.w * q.x; acc[3][1] += a.w * q.y; acc[3][2] += a.w * q.z; acc[3][3] += a.w * q.w;
        }
        __syncthreads();
    }

    // epilogue: bias, store, per-channel partial stats (smem reuse after sync)
    float* red_s  = Ws;   // [co*17+tx]
    float* red_ss = Xs;
    #pragma unroll
    for (int j = 0; j < 4; j++) {
        int co = ty * 4 + j;
        float bb = bias[co];
        float x0 = acc[j][0] + bb, x1 = acc[j][1] + bb;
        float x2 = acc[j][2] + bb, x3 = acc[j][3] + bb;
        *(float4*)&y[((size_t)(b * 64 + co)) * N_ + n0 + tx * 4] = make_float4(x0, x1, x2, x3);
        red_s[co * 17 + tx]  = x0 + x1 + x2 + x3;
        red_ss[co * 17 + tx] = x0 * x0 + x1 * x1 + x2 * x2 + x3 * x3;
    }
    __syncthreads();
    if (tid < 64) {
        float S = 0.f, SS = 0.f;
        #pragma unroll
        for (int i = 0; i < 16; i++) { S += red_s[tid * 17 + i]; SS += red_ss[tid * 17 + i]; }
        if (which == 2) {
            g_vpart[(b * 64 + tid) * 64 + blockIdx.x] = S;
        } else {
            int o = which * 64 + tid;
            g_spart[o * 512 + b * 64 + blockIdx.x]  = S;
            g_sspart[o * 512 + b * 64 + blockIdx.x] = SS;
        }
    }
}

// ---------------- K2: reduce partials -> BN scale/shift, vsum ----------------
__global__ __launch_bounds__(128) void stats_reduce_kernel(
    const float* __restrict__ gamma, const float* __restrict__ beta)
{
    int gid = blockIdx.x * 128 + threadIdx.x;
    if (gid < 128) {
        int c = gid & 63;
        float S = 0.f, SS = 0.f;
        #pragma unroll 8
        for (int i = 0; i < 512; i++) {
            S  += g_spart[gid * 512 + i];
            SS += g_sspart[gid * 512 + i];
        }
        const float inv = 1.0f / 32768.0f;
        float mean = S * inv;
        float var  = SS * inv - mean * mean;
        float sc = gamma[c] * rsqrtf(var + 1e-5f);
        g_scale[gid] = sc;
        g_shift[gid] = beta[c] - mean * sc;
    } else if (gid < 640) {
        int t = gid - 128;
        float S = 0.f;
        #pragma unroll
        for (int i = 0; i < 64; i++) S += g_vpart[t * 64 + i];
        g_vsum[t] = S;
    }
}

// ---------------- K3: per-column rnorm (stats only, no rewrite) -------------
// 512 blocks x 128 threads; thread owns one (which,b,n) column.
__global__ __launch_bounds__(128) void colstats_kernel() {
    int gid = blockIdx.x * 128 + threadIdx.x;     // 0..65535
    int which = gid >> 15;
    int r = gid & 32767;
    int b = r >> 12;
    int n = r & (N_ - 1);
    const float* y = which ? g_yk : g_yq;

    __shared__ float scs[64], shs[64];
    if (threadIdx.x < 64) {
        scs[threadIdx.x] = g_scale[which * 64 + threadIdx.x];
        shs[threadIdx.x] = g_shift[which * 64 + threadIdx.x];
    }
    __syncthreads();

    float ss = 0.f;
    #pragma unroll 8
    for (int c = 0; c < 64; c++) {
        float t = y[((size_t)(b * 64 + c)) * N_ + n] * scs[c] + shs[c];
        ss += t * t;
    }
    g_rn[(which * B_ + b) * N_ + n] = 1.0f / (sqrtf(ss) + 1e-7f);
}

// ---------------- K4: KV partials, BN+norm fused on K load ------------------
__global__ __launch_bounds__(256) void kv_kernel() {
    int chunk = blockIdx.x, b = blockIdx.y;
    __shared__ float Ks[64][65];
    __shared__ float Vs[64][65];
    int tid = threadIdx.x;
    int ty = tid >> 4, tx = tid & 15;
    int nn = tid & 63;            // fixed column per thread in load phase
    int c0 = tid >> 6;            // warp-uniform channel base
    float acc[4][4] = {};

    for (int t = 0; t < 2; t++) {
        int n0 = chunk * 128 + t * 64;
        float rn = g_rn[((size_t)(B_ + b)) * N_ + n0 + nn];   // k-side rnorm
        #pragma unroll
        for (int i = 0; i < 16; i++) {
            int c = c0 + i * 4;                               // warp-uniform
            float sc = g_scale[64 + c], sh = g_shift[64 + c]; // broadcast LDG
            float kraw = g_yk[((size_t)(b * 64 + c)) * N_ + n0 + nn];
            Ks[c][nn] = (kraw * sc + sh) * rn;
            Vs[c][nn] = g_yv[((size_t)(b * 64 + c)) * N_ + n0 + nn];
        }
        __syncthreads();
        #pragma unroll 8
        for (int n = 0; n < 64; n++) {
            float kv[4], vv[4];
            #pragma unroll
            for (int j = 0; j < 4; j++) kv[j] = Ks[ty + j * 16][n];
            #pragma unroll
            for (int j = 0; j < 4; j++) vv[j] = Vs[tx + j * 16][n];
            #pragma unroll
            for (int j = 0; j < 4; j++)
                #pragma unroll
                for (int i = 0; i < 4; i++)
                    acc[j][i] += kv[j] * vv[i];
        }
        __syncthreads();
    }
    #pragma unroll
    for (int j = 0; j < 4; j++)
        #pragma unroll
        for (int i = 0; i < 4; i++)
            g_kvpart[(((size_t)chunk * B_ + b) * 64 + ty + j * 16) * 64 + tx + i * 16] = acc[j][i];
}

// ---------------- K5: per-batch M = KV @ Ww^T, obias = vsum@Ww^T + bw --------
__global__ __launch_bounds__(256) void m_kernel(
    const float* __restrict__ Ww, const float* __restrict__ bw)
{
    int b = blockIdx.x;
    __shared__ float KVs[64][64];
    __shared__ float WwT[64][128];
    int tid = threadIdx.x;

    for (int e = tid; e < 4096; e += 256) {
        float s = 0.f;
        #pragma unroll
        for (int c2 = 0; c2 < KVCHUNKS; c2++)
            s += g_kvpart[((size_t)c2 * B_ + b) * 4096 + e];
        KVs[e >> 6][e & 63] = s;
    }
    for (int e = tid; e < 8192; e += 256) {
        int cv = e >> 7, co = e & 127;
        WwT[cv][co] = Ww[co * CV + cv];
    }
    __syncthreads();

    int co = tid & 127;
    for (int ck = (tid >> 7); ck < 64; ck += 2) {
        float s = 0.f;
        #pragma unroll 8
        for (int cv = 0; cv < 64; cv++) s += KVs[ck][cv] * WwT[cv][co];
        g_M[((size_t)b * 64 + ck) * CO + co] = s;
    }
    if (tid < 128) {
        float s = bw[tid];
        #pragma unroll 8
        for (int cv = 0; cv < 64; cv++) s += g_vsum[b * 64 + cv] * WwT[cv][tid];
        g_obias[b * CO + tid] = s;
    }
}

// ---------------- K6: out = qnorm^T @ M + obias, BN+norm fused on Q load ----
__global__ __launch_bounds__(256) void out_kernel(float* __restrict__ out) {
    int b = blockIdx.y, n0 = blockIdx.x * 64;
    int tid = threadIdx.x;
    int ty = tid >> 4, tx = tid & 15;
    int nn = tid & 63;
    int c0 = tid >> 6;
    __shared__ float Ms[64][128];   // 32 KB
    __shared__ float Qs[64][64];    // 16 KB (total exactly 48 KB)

    for (int e = tid; e < 8192; e += 256)
        Ms[e >> 7][e & 127] = g_M[(size_t)b * 8192 + e];

    float rn = g_rn[(size_t)b * N_ + n0 + nn];                // q-side rnorm
    #pragma unroll
    for (int i = 0; i < 16; i++) {
        int ck = c0 + i * 4;                                  // warp-uniform
        float sc = g_scale[ck], sh = g_shift[ck];             // broadcast LDG
        float qraw = g_yq[((size_t)(b * 64 + ck)) * N_ + n0 + nn];
        Qs[ck][nn] = (qraw * sc + sh) * rn;
    }
    __syncthreads();

    float acc[8][4] = {};
    #pragma unroll 8
    for (int ck = 0; ck < 64; ck++) {
        float4 a0 = *(const float4*)&Ms[ck][ty * 8];
        float4 a1 = *(const float4*)&Ms[ck][ty * 8 + 4];
        float4 q  = *(const float4*)&Qs[ck][tx * 4];
        acc[0][0] += a0.x * q.x; acc[0][1] += a0.x * q.y; acc[0][2] += a0.x * q.z; acc[0][3] += a0.x * q.w;
        acc[1][0] += a0.y * q.x; acc[1][1] += a0.y * q.y; acc[1][2] += a0.y * q.z; acc[1][3] += a0.y * q.w;
        acc[2][0] += a0.z * q.x; acc[2][1] += a0.z * q.y; acc[2][2] += a0.z * q.z; acc[2][3] += a0.z * q.w;
        acc[3][0] += a0.w * q.x; acc[3][1] += a0.w * q.y; acc[3][2] += a0.w * q.z; acc[3][3] += a0.w * q.w;
        acc[4][0] += a1.x * q.x; acc[4][1] += a1.x * q.y; acc[4][2] += a1.x * q.z; acc[4][3] += a1.x * q.w;
        acc[5][0] += a1.y * q.x; acc[5][1] += a1.y * q.y; acc[5][2] += a1.y * q.z; acc[5][3] += a1.y * q.w;
        acc[6][0] += a1.z * q.x; acc[6][1] += a1.z * q.y; acc[6][2] += a1.z * q.z; acc[6][3] += a1.z * q.w;
        acc[7][0] += a1.w * q.x; acc[7][1] += a1.w * q.y; acc[7][2] += a1.w * q.z; acc[7][3] += a1.w * q.w;
    }
    #pragma unroll
    for (int j = 0; j < 8; j++) {
        int co = ty * 8 + j;
        float ob = g_obias[b * CO + co];
        float4 o = make_float4(acc[j][0] + ob, acc[j][1] + ob, acc[j][2] + ob, acc[j][3] + ob);
        *(float4*)&out[((size_t)(b * CO + co)) * N_ + n0 + tx * 4] = o;
    }
}

// ---------------- launch ----------------
extern "C" void kernel_launch(void* const* d_in, const int* in_sizes, int n_in,
                              void* d_out, int out_size) {
    const float* q     = (const float*)d_in[0];
    const float* k     = (const float*)d_in[1];
    const float* v     = (const float*)d_in[2];
    const float* Wk    = (const float*)d_in[3];
    const float* bk    = (const float*)d_in[4];
    const float* gamma = (const float*)d_in[5];
    const float* beta  = (const float*)d_in[6];
    const float* Wv    = (const float*)d_in[7];
    const float* bv    = (const float*)d_in[8];
    const float* Ww    = (const float*)d_in[9];
    const float* bw    = (const float*)d_in[10];
    float* out = (float*)d_out;

    prep_kernel<<<64, 256>>>(Wk, Wv);
    conv_kernel<<<dim3(64, B_, 3), 256>>>(q, k, v, bk, bv);
    stats_reduce_kernel<<<5, 128>>>(gamma, beta);
    colstats_kernel<<<512, 128>>>();
    kv_kernel<<<dim3(KVCHUNKS, B_), 256>>>();
    m_kernel<<<B_, 256>>>(Ww, bw);
    out_kernel<<<dim3(64, B_), 256>>>(out);
}

// round 7
// speedup vs baseline: 1.4200x; 1.4200x over previous
#include <cuda_runtime.h>
#include <math.h>

#define B_   8
#define CIN  128
#define CK   64
#define CV   64
#define CO   128
#define N_   4096
#define KVCHUNKS 32

// ---------------- scratch ----------------
__device__ float g_yq[B_ * CK * N_];
__device__ float g_yk[B_ * CK * N_];
__device__ float g_yv[B_ * CV * N_];
__device__ float g_WkT[CIN * CK];
__device__ float g_WvT[CIN * CV];
__device__ float g_scale[2 * CK];
__device__ float g_shift[2 * CK];
__device__ float g_vsumpart[KVCHUNKS * B_ * CV];  // per-chunk V row sums
__device__ float g_kvpart[KVCHUNKS * B_ * CK * CV];
__device__ float g_M[B_ * CK * CO];
__device__ float g_obias[B_ * CO];

// ---------------- K0: transpose weights ----------------
__global__ void prep_kernel(const float* __restrict__ Wk, const float* __restrict__ Wv) {
    int idx = blockIdx.x * 256 + threadIdx.x;
    int which = idx >> 13;
    int r = idx & 8191;
    int ci = r >> 6, co = r & 63;
    float v = which ? Wv[co * CIN + ci] : Wk[co * CIN + ci];
    if (which) g_WvT[ci * 64 + co] = v;
    else       g_WkT[ci * 64 + co] = v;
}

// ---------------- K1: 1x1 conv (R1 form, unchanged) --------------------------
// grid (64, B_, 3), 256 threads. Tile 64co x 64n, thread tile 4x4.
__global__ __launch_bounds__(256) void conv_kernel(
    const float* __restrict__ xq, const float* __restrict__ xk,
    const float* __restrict__ xv,
    const float* __restrict__ bk, const float* __restrict__ bv)
{
    int which = blockIdx.z;
    const float* x    = (which == 0) ? xq : (which == 1) ? xk : xv;
    const float* WT   = (which == 2) ? g_WvT : g_WkT;
    const float* bias = (which == 2) ? bv : bk;
    float* y          = (which == 0) ? g_yq : (which == 1) ? g_yk : g_yv;

    int b  = blockIdx.y;
    int n0 = blockIdx.x * 64;
    int tid = threadIdx.x;
    int ty = tid >> 4, tx = tid & 15;

    __shared__ float Ws[64][64];
    __shared__ float Xs[64][64];

    float acc[4][4] = {};

    for (int s = 0; s < 2; s++) {
        #pragma unroll
        for (int i = 0; i < 16; i++) {
            int idx = tid + i * 256;
            int cik = idx >> 6, nn = idx & 63;
            Xs[cik][nn] = x[((size_t)(b * CIN + s * 64 + cik)) * N_ + n0 + nn];
            Ws[cik][nn] = WT[(s * 64 + cik) * 64 + nn];
        }
        __syncthreads();
        #pragma unroll 16
        for (int ci = 0; ci < 64; ci++) {
            float4 a = *(const float4*)&Ws[ci][ty * 4];
            float4 q = *(const float4*)&Xs[ci][tx * 4];
            acc[0][0] += a.x * q.x; acc[0][1] += a.x * q.y; acc[0][2] += a.x * q.z; acc[0][3] += a.x * q.w;
            acc[1][0] += a.y * q.x; acc[1][1] += a.y * q.y; acc[1][2] += a.y * q.z; acc[1][3] += a.y * q.w;
            acc[2][0] += a.z * q.x; acc[2][1] += a.z * q.y; acc[2][2] += a.z * q.z; acc[2][3] += a.z * q.w;
            acc[3][0] += a.w * q.x; acc[3][1] += a.w * q.y; acc[3][2] += a.w * q.z; acc[3][3] += a.w * q.w;
        }
        __syncthreads();
    }
    #pragma unroll
    for (int j = 0; j < 4; j++) {
        int co = ty * 4 + j;
        float bb = bias[co];
        float4 o = make_float4(acc[j][0] + bb, acc[j][1] + bb, acc[j][2] + bb, acc[j][3] + bb);
        *(float4*)&y[((size_t)(b * 64 + co)) * N_ + n0 + tx * 4] = o;
    }
}

// ---------------- K2: BN batch stats (float4 loads, high MLP) ----------------
// grid 128 (which*64+c), 256 threads
__global__ __launch_bounds__(256) void bn_stats_kernel(
    const float* __restrict__ gamma, const float* __restrict__ beta)
{
    int c = blockIdx.x & 63;
    int which = blockIdx.x >> 6;
    const float* y = which ? g_yk : g_yq;
    int tid = threadIdx.x;

    float s = 0.f, ss = 0.f;
    #pragma unroll
    for (int b = 0; b < B_; b++) {
        const float4* row = (const float4*)(y + ((size_t)(b * 64 + c)) * N_);
        #pragma unroll
        for (int i = 0; i < 4; i++) {
            float4 f = row[tid + i * 256];
            s  += f.x + f.y + f.z + f.w;
            ss += f.x * f.x + f.y * f.y + f.z * f.z + f.w * f.w;
        }
    }
    #pragma unroll
    for (int o = 16; o; o >>= 1) {
        s  += __shfl_down_sync(0xffffffffu, s, o);
        ss += __shfl_down_sync(0xffffffffu, ss, o);
    }
    __shared__ float rs[8], rss[8];
    int wid = tid >> 5, lane = tid & 31;
    if (lane == 0) { rs[wid] = s; rss[wid] = ss; }
    __syncthreads();
    if (tid == 0) {
        float S = 0.f, SS = 0.f;
        #pragma unroll
        for (int i = 0; i < 8; i++) { S += rs[i]; SS += rss[i]; }
        const float inv = 1.0f / 32768.0f;
        float mean = S * inv;
        float var  = SS * inv - mean * mean;
        float sc = gamma[c] * rsqrtf(var + 1e-5f);
        g_scale[blockIdx.x] = sc;
        g_shift[blockIdx.x] = beta[c] - mean * sc;
    }
}

// ---------------- K3: apply BN + L2-normalize (2 threads/column) -------------
// grid 512 (256 per which), 256 threads; block handles 128 columns.
__global__ __launch_bounds__(256) void norm_kernel() {
    int colblk = blockIdx.x;
    int which = colblk >> 8;
    int r = colblk & 255;
    int b = r >> 5;
    int n0 = (r & 31) * 128;
    float* y = which ? g_yk : g_yq;
    int tid = threadIdx.x;
    int half = tid >> 7;          // 0: channels 0-31, 1: channels 32-63
    int l = tid & 127;            // column within block
    int n = n0 + l;

    __shared__ float scs[64], shs[64], ss2[2][128];
    if (tid < 64) {
        scs[tid] = g_scale[which * 64 + tid];
        shs[tid] = g_shift[which * 64 + tid];
    }
    __syncthreads();

    float v[32];
    float ss = 0.f;
    #pragma unroll
    for (int i = 0; i < 32; i++) {
        int c = half * 32 + i;
        float t = y[((size_t)(b * 64 + c)) * N_ + n] * scs[c] + shs[c];
        v[i] = t; ss += t * t;
    }
    ss2[half][l] = ss;
    __syncthreads();
    float rn = 1.0f / (sqrtf(ss2[0][l] + ss2[1][l]) + 1e-7f);
    #pragma unroll
    for (int i = 0; i < 32; i++)
        y[((size_t)(b * 64 + half * 32 + i)) * N_ + n] = v[i] * rn;
}

// ---------------- K4: KV partials + fused V-row sum partials -----------------
// grid (KVCHUNKS, B_), 256 threads
__global__ __launch_bounds__(256) void kv_kernel() {
    int chunk = blockIdx.x, b = blockIdx.y;
    __shared__ float Ks[64][65];
    __shared__ float Vs[64][65];
    __shared__ float vps[64][4];
    int tid = threadIdx.x;
    int ty = tid >> 4, tx = tid & 15;
    int cc = tid & 63, q4 = tid >> 6;
    float acc[4][4] = {};
    float vp = 0.f;

    for (int t = 0; t < 2; t++) {
        int n0 = chunk * 128 + t * 64;
        #pragma unroll
        for (int i = 0; i < 16; i++) {
            int idx = tid + i * 256;
            int c = idx >> 6, nn = idx & 63;
            Ks[c][nn] = g_yk[((size_t)(b * 64 + c)) * N_ + n0 + nn];
            Vs[c][nn] = g_yv[((size_t)(b * 64 + c)) * N_ + n0 + nn];
        }
        __syncthreads();
        #pragma unroll 8
        for (int n = 0; n < 64; n++) {
            float kv[4], vv[4];
            #pragma unroll
            for (int j = 0; j < 4; j++) kv[j] = Ks[ty + j * 16][n];
            #pragma unroll
            for (int j = 0; j < 4; j++) vv[j] = Vs[tx + j * 16][n];
            #pragma unroll
            for (int j = 0; j < 4; j++)
                #pragma unroll
                for (int i = 0; i < 4; i++)
                    acc[j][i] += kv[j] * vv[i];
        }
        // fused V-row partial sums (thread owns row cc, quarter q4)
        #pragma unroll
        for (int i = 0; i < 16; i++) vp += Vs[cc][q4 * 16 + i];
        __syncthreads();
    }
    #pragma unroll
    for (int j = 0; j < 4; j++)
        #pragma unroll
        for (int i = 0; i < 4; i++)
            g_kvpart[(((size_t)chunk * B_ + b) * 64 + ty + j * 16) * 64 + tx + i * 16] = acc[j][i];

    vps[cc][q4] = vp;
    __syncthreads();
    if (tid < 64)
        g_vsumpart[((size_t)chunk * B_ + b) * 64 + tid] =
            vps[tid][0] + vps[tid][1] + vps[tid][2] + vps[tid][3];
}

// ---------------- K5: per-batch M = KV @ Ww^T, obias = vsum@Ww^T + bw --------
__global__ __launch_bounds__(256) void m_kernel(
    const float* __restrict__ Ww, const float* __restrict__ bw)
{
    int b = blockIdx.x;
    __shared__ float KVs[64][64];
    __shared__ float WwT[64][128];
    __shared__ float vs_s[64];
    int tid = threadIdx.x;

    if (tid < 64) {
        float S = 0.f;
        #pragma unroll
        for (int c2 = 0; c2 < KVCHUNKS; c2++)
            S += g_vsumpart[((size_t)c2 * B_ + b) * 64 + tid];
        vs_s[tid] = S;
    }
    for (int e = tid; e < 4096; e += 256) {
        float s = 0.f;
        #pragma unroll
        for (int c2 = 0; c2 < KVCHUNKS; c2++)
            s += g_kvpart[((size_t)c2 * B_ + b) * 4096 + e];
        KVs[e >> 6][e & 63] = s;
    }
    for (int e = tid; e < 8192; e += 256) {
        int cv = e >> 7, co = e & 127;
        WwT[cv][co] = Ww[co * CV + cv];
    }
    __syncthreads();

    int co = tid & 127;
    for (int ck = (tid >> 7); ck < 64; ck += 2) {
        float s = 0.f;
        #pragma unroll 8
        for (int cv = 0; cv < 64; cv++) s += KVs[ck][cv] * WwT[cv][co];
        g_M[((size_t)b * 64 + ck) * CO + co] = s;
    }
    if (tid < 128) {
        float s = bw[tid];
        #pragma unroll 8
        for (int cv = 0; cv < 64; cv++) s += vs_s[cv] * WwT[cv][tid];
        g_obias[b * CO + tid] = s;
    }
}

// ---------------- K6: out = qnorm^T @ M + obias (R1 form) --------------------
__global__ __launch_bounds__(256) void out_kernel(float* __restrict__ out) {
    int b = blockIdx.y, n0 = blockIdx.x * 64;
    int tid = threadIdx.x;
    int ty = tid >> 4, tx = tid & 15;
    __shared__ float Ms[64][128];
    __shared__ float Qs[64][64];

    for (int e = tid; e < 8192; e += 256)
        Ms[e >> 7][e & 127] = g_M[(size_t)b * 8192 + e];
    for (int e = tid; e < 4096; e += 256)
        Qs[e >> 6][e & 63] = g_yq[((size_t)(b * 64 + (e >> 6))) * N_ + n0 + (e & 63)];
    __syncthreads();

    float acc[8][4] = {};
    #pragma unroll 8
    for (int ck = 0; ck < 64; ck++) {
        float4 a0 = *(const float4*)&Ms[ck][ty * 8];
        float4 a1 = *(const float4*)&Ms[ck][ty * 8 + 4];
        float4 q  = *(const float4*)&Qs[ck][tx * 4];
        acc[0][0] += a0.x * q.x; acc[0][1] += a0.x * q.y; acc[0][2] += a0.x * q.z; acc[0][3] += a0.x * q.w;
        acc[1][0] += a0.y * q.x; acc[1][1] += a0.y * q.y; acc[1][2] += a0.y * q.z; acc[1][3] += a0.y * q.w;
        acc[2][0] += a0.z * q.x; acc[2][1] += a0.z * q.y; acc[2][2] += a0.z * q.z; acc[2][3] += a0.z * q.w;
        acc[3][0] += a0.w * q.x; acc[3][1] += a0.w * q.y; acc[3][2] += a0.w * q.z; acc[3][3] += a0.w * q.w;
        acc[4][0] += a1.x * q.x; acc[4][1] += a1.x * q.y; acc[4][2] += a1.x * q.z; acc[4][3] += a1.x * q.w;
        acc[5][0] += a1.y * q.x; acc[5][1] += a1.y * q.y; acc[5][2] += a1.y * q.z; acc[5][3] += a1.y * q.w;
        acc[6][0] += a1.z * q.x; acc[6][1] += a1.z * q.y; acc[6][2] += a1.z * q.z; acc[6][3] += a1.z * q.w;
        acc[7][0] += a1.w * q.x; acc[7][1] += a1.w * q.y; acc[7][2] += a1.w * q.z; acc[7][3] += a1.w * q.w;
    }
    #pragma unroll
    for (int j = 0; j < 8; j++) {
        int co = ty * 8 + j;
        float ob = g_obias[b * CO + co];
        float4 o = make_float4(acc[j][0] + ob, acc[j][1] + ob, acc[j][2] + ob, acc[j][3] + ob);
        *(float4*)&out[((size_t)(b * CO + co)) * N_ + n0 + tx * 4] = o;
    }
}

// ---------------- launch ----------------
extern "C" void kernel_launch(void* const* d_in, const int* in_sizes, int n_in,
                              void* d_out, int out_size) {
    const float* q     = (const float*)d_in[0];
    const float* k     = (const float*)d_in[1];
    const float* v     = (const float*)d_in[2];
    const float* Wk    = (const float*)d_in[3];
    const float* bk    = (const float*)d_in[4];
    const float* gamma = (const float*)d_in[5];
    const float* beta  = (const float*)d_in[6];
    const float* Wv    = (const float*)d_in[7];
    const float* bv    = (const float*)d_in[8];
    const float* Ww    = (const float*)d_in[9];
    const float* bw    = (const float*)d_in[10];
    float* out = (float*)d_out;

    prep_kernel<<<64, 256>>>(Wk, Wv);
    conv_kernel<<<dim3(64, B_, 3), 256>>>(q, k, v, bk, bv);
    bn_stats_kernel<<<128, 256>>>(gamma, beta);
    norm_kernel<<<512, 256>>>();
    kv_kernel<<<dim3(KVCHUNKS, B_), 256>>>();
    m_kernel<<<B_, 256>>>(Ww, bw);
    out_kernel<<<dim3(64, B_), 256>>>(out);
}

// round 8
// speedup vs baseline: 1.7430x; 1.2275x over previous
#include <cuda_runtime.h>
#include <cuda_bf16.h>
#include <math.h>

#define B_   8
#define CIN  128
#define CK   64
#define CV   64
#define CO   128
#define N_   4096
#define KVCHUNKS 32

// ---------------- scratch ----------------
__device__ float g_yq[B_ * CK * N_];
__device__ float g_yk[B_ * CK * N_];
__device__ float g_yv[B_ * CV * N_];
__device__ float g_scale[2 * CK];
__device__ float g_shift[2 * CK];
__device__ float g_vsumpart[KVCHUNKS * B_ * CV];
__device__ float g_kvpart[KVCHUNKS * B_ * CK * CV];
__device__ float g_M[B_ * CK * CO];
__device__ float g_obias[B_ * CO];

// ---------------- mma / ldmatrix helpers ----------------
__device__ __forceinline__ unsigned su32(const void* p) {
    return (unsigned)__cvta_generic_to_shared(p);
}
#define LDSM_X4(r, addr) \
    asm volatile("ldmatrix.sync.aligned.m8n8.x4.shared.b16 {%0,%1,%2,%3}, [%4];" \
        : "=r"((r)[0]), "=r"((r)[1]), "=r"((r)[2]), "=r"((r)[3]) : "r"(addr))
#define LDSM_X4T(r, addr) \
    asm volatile("ldmatrix.sync.aligned.m8n8.x4.trans.shared.b16 {%0,%1,%2,%3}, [%4];" \
        : "=r"((r)[0]), "=r"((r)[1]), "=r"((r)[2]), "=r"((r)[3]) : "r"(addr))
#define MMA_BF16(d, a, b0, b1) \
    asm volatile("mma.sync.aligned.m16n8k16.row.col.f32.bf16.bf16.f32 " \
        "{%0,%1,%2,%3}, {%4,%5,%6,%7}, {%8,%9}, {%0,%1,%2,%3};" \
        : "+f"((d)[0]), "+f"((d)[1]), "+f"((d)[2]), "+f"((d)[3]) \
        : "r"((a)[0]), "r"((a)[1]), "r"((a)[2]), "r"((a)[3]), "r"(b0), "r"(b1))

__device__ __forceinline__ unsigned packbf(__nv_bfloat16 lo, __nv_bfloat16 hi) {
    return ((unsigned)__bfloat16_as_ushort(hi) << 16) | __bfloat16_as_ushort(lo);
}
// split float4 into bf16 hi (uint2) and residual lo (uint2)
__device__ __forceinline__ void split4(float4 f, uint2 &hi, uint2 &lo) {
    __nv_bfloat16 hx = __float2bfloat16(f.x), hy = __float2bfloat16(f.y);
    __nv_bfloat16 hz = __float2bfloat16(f.z), hw = __float2bfloat16(f.w);
    __nv_bfloat16 lx = __float2bfloat16(f.x - __bfloat162float(hx));
    __nv_bfloat16 ly = __float2bfloat16(f.y - __bfloat162float(hy));
    __nv_bfloat16 lz = __float2bfloat16(f.z - __bfloat162float(hz));
    __nv_bfloat16 lw = __float2bfloat16(f.w - __bfloat162float(hw));
    hi.x = packbf(hx, hy); hi.y = packbf(hz, hw);
    lo.x = packbf(lx, ly); lo.y = packbf(lz, lw);
}

// ---------------- K1: 1x1 conv via bf16-split tensor-core MMA ----------------
// grid (64, B_, 3), 256 threads (8 warps). Tile 64co x 64n, K=128 in 2 stages.
// Y = (Ah+Al)(Bh+Bl) approx Ah*Bh + Ah*Bl + Al*Bh.
#define ASTR 72   // bf16 per A row (64 + 8 pad), 144 bytes
#define BSTR 72
__global__ __launch_bounds__(256) void conv_mma_kernel(
    const float* __restrict__ xq, const float* __restrict__ xk,
    const float* __restrict__ xv,
    const float* __restrict__ Wk, const float* __restrict__ Wv,
    const float* __restrict__ bk, const float* __restrict__ bv)
{
    int which = blockIdx.z;
    const float* x    = (which == 0) ? xq : (which == 1) ? xk : xv;
    const float* W    = (which == 2) ? Wv : Wk;     // [64 co][128 ci] row-major
    const float* bias = (which == 2) ? bv : bk;
    float* y          = (which == 0) ? g_yq : (which == 1) ? g_yk : g_yv;

    int bb = blockIdx.y;
    int n0 = blockIdx.x * 64;
    int tid = threadIdx.x;
    int lane = tid & 31, w = tid >> 5;
    int ct = (w & 3) * 16;            // co tile base
    int ng = (w >> 2) * 32;           // n half base

    __shared__ __align__(16) __nv_bfloat16 Ah[64 * ASTR];  // [co][ci_local]
    __shared__ __align__(16) __nv_bfloat16 Al[64 * ASTR];
    __shared__ __align__(16) __nv_bfloat16 Bh[64 * BSTR];  // [ci_local][n]
    __shared__ __align__(16) __nv_bfloat16 Bl[64 * BSTR];

    // per-lane ldmatrix addresses (offsets constant across stages)
    int q = lane >> 3, rr = lane & 7;
    unsigned aOffH, aOffL, bOffH0, bOffL0, bOffH1, bOffL1;
    {
        int arow = ct + (q & 1) * 8 + rr;
        int acol = (q >> 1) * 8;
        aOffH = su32(Ah) + arow * (ASTR * 2) + acol * 2;
        aOffL = su32(Al) + arow * (ASTR * 2) + acol * 2;
        int brow = (q & 1) * 8 + rr;                 // k-local within step
        int bcol0 = ng + (q >> 1) * 8;               // ntiles 0,1
        int bcol1 = ng + 16 + (q >> 1) * 8;          // ntiles 2,3
        bOffH0 = su32(Bh) + brow * (BSTR * 2) + bcol0 * 2;
        bOffL0 = su32(Bl) + brow * (BSTR * 2) + bcol0 * 2;
        bOffH1 = su32(Bh) + brow * (BSTR * 2) + bcol1 * 2;
        bOffL1 = su32(Bl) + brow * (BSTR * 2) + bcol1 * 2;
    }

    float acc[4][4] = {};   // 4 ntiles x 4 regs

    for (int s = 0; s < 2; s++) {
        // stage W: 64co x 64ci floats -> Ah/Al
        #pragma unroll
        for (int i = 0; i < 4; i++) {
            int e = tid + i * 256;                  // float4 index 0..1023
            int co = e >> 4, ci4 = (e & 15) * 4;
            float4 f = *(const float4*)&W[co * CIN + s * 64 + ci4];
            uint2 hi, lo; split4(f, hi, lo);
            *(uint2*)&Ah[co * ASTR + ci4] = hi;
            *(uint2*)&Al[co * ASTR + ci4] = lo;
        }
        // stage X: 64ci x 64n floats -> Bh/Bl  (row ci, cols n)
        #pragma unroll
        for (int i = 0; i < 4; i++) {
            int e = tid + i * 256;
            int ci = e >> 4, nn4 = (e & 15) * 4;
            float4 f = *(const float4*)&x[((size_t)(bb * CIN + s * 64 + ci)) * N_ + n0 + nn4];
            uint2 hi, lo; split4(f, hi, lo);
            *(uint2*)&Bh[ci * BSTR + nn4] = hi;
            *(uint2*)&Bl[ci * BSTR + nn4] = lo;
        }
        __syncthreads();

        #pragma unroll
        for (int ks = 0; ks < 4; ks++) {
            unsigned aStep = ks * 32;               // 16 bf16 = 32 bytes
            unsigned bStep = ks * 16 * (BSTR * 2);  // 16 rows
            unsigned ah[4], al[4], bh[4], bl[4], bh2[4], bl2[4];
            LDSM_X4(ah, aOffH + aStep);
            LDSM_X4(al, aOffL + aStep);
            LDSM_X4T(bh, bOffH0 + bStep);
            LDSM_X4T(bl, bOffL0 + bStep);
            LDSM_X4T(bh2, bOffH1 + bStep);
            LDSM_X4T(bl2, bOffL1 + bStep);
            // ntile 0: bh[0],bh[1]; ntile 1: bh[2],bh[3]; etc.
            MMA_BF16(acc[0], ah, bh[0], bh[1]);
            MMA_BF16(acc[0], ah, bl[0], bl[1]);
            MMA_BF16(acc[0], al, bh[0], bh[1]);
            MMA_BF16(acc[1], ah, bh[2], bh[3]);
            MMA_BF16(acc[1], ah, bl[2], bl[3]);
            MMA_BF16(acc[1], al, bh[2], bh[3]);
            MMA_BF16(acc[2], ah, bh2[0], bh2[1]);
            MMA_BF16(acc[2], ah, bl2[0], bl2[1]);
            MMA_BF16(acc[2], al, bh2[0], bh2[1]);
            MMA_BF16(acc[3], ah, bh2[2], bh2[3]);
            MMA_BF16(acc[3], ah, bl2[2], bl2[3]);
            MMA_BF16(acc[3], al, bh2[2], bh2[3]);
        }
        __syncthreads();
    }

    // epilogue: D(row, col): row = ct + lane/4 (+8), col = ng + t*8 + 2*(lane%4)
    int r4 = lane >> 2, c2 = (lane & 3) * 2;
    int row0 = ct + r4, row1 = ct + r4 + 8;
    float b0v = bias[row0], b1v = bias[row1];
    #pragma unroll
    for (int t = 0; t < 4; t++) {
        int col = n0 + ng + t * 8 + c2;
        *(float2*)&y[((size_t)(bb * 64 + row0)) * N_ + col] =
            make_float2(acc[t][0] + b0v, acc[t][1] + b0v);
        *(float2*)&y[((size_t)(bb * 64 + row1)) * N_ + col] =
            make_float2(acc[t][2] + b1v, acc[t][3] + b1v);
    }
}

// ---------------- K2: BN batch stats (float4 loads) ----------------
__global__ __launch_bounds__(256) void bn_stats_kernel(
    const float* __restrict__ gamma, const float* __restrict__ beta)
{
    int c = blockIdx.x & 63;
    int which = blockIdx.x >> 6;
    const float* y = which ? g_yk : g_yq;
    int tid = threadIdx.x;

    float s = 0.f, ss = 0.f;
    #pragma unroll
    for (int b = 0; b < B_; b++) {
        const float4* row = (const float4*)(y + ((size_t)(b * 64 + c)) * N_);
        #pragma unroll
        for (int i = 0; i < 4; i++) {
            float4 f = row[tid + i * 256];
            s  += f.x + f.y + f.z + f.w;
            ss += f.x * f.x + f.y * f.y + f.z * f.z + f.w * f.w;
        }
    }
    #pragma unroll
    for (int o = 16; o; o >>= 1) {
        s  += __shfl_down_sync(0xffffffffu, s, o);
        ss += __shfl_down_sync(0xffffffffu, ss, o);
    }
    __shared__ float rs[8], rss[8];
    int wid = tid >> 5, lane = tid & 31;
    if (lane == 0) { rs[wid] = s; rss[wid] = ss; }
    __syncthreads();
    if (tid == 0) {
        float S = 0.f, SS = 0.f;
        #pragma unroll
        for (int i = 0; i < 8; i++) { S += rs[i]; SS += rss[i]; }
        const float inv = 1.0f / 32768.0f;
        float mean = S * inv;
        float var  = SS * inv - mean * mean;
        float sc = gamma[c] * rsqrtf(var + 1e-5f);
        g_scale[blockIdx.x] = sc;
        g_shift[blockIdx.x] = beta[c] - mean * sc;
    }
}

// ---------------- K3: apply BN + L2-normalize (2 threads/column) -------------
__global__ __launch_bounds__(256) void norm_kernel() {
    int colblk = blockIdx.x;
    int which = colblk >> 8;
    int r = colblk & 255;
    int b = r >> 5;
    int n0 = (r & 31) * 128;
    float* y = which ? g_yk : g_yq;
    int tid = threadIdx.x;
    int half = tid >> 7;
    int l = tid & 127;
    int n = n0 + l;

    __shared__ float scs[64], shs[64], ss2[2][128];
    if (tid < 64) {
        scs[tid] = g_scale[which * 64 + tid];
        shs[tid] = g_shift[which * 64 + tid];
    }
    __syncthreads();

    float v[32];
    float ss = 0.f;
    #pragma unroll
    for (int i = 0; i < 32; i++) {
        int c = half * 32 + i;
        float t = y[((size_t)(b * 64 + c)) * N_ + n] * scs[c] + shs[c];
        v[i] = t; ss += t * t;
    }
    ss2[half][l] = ss;
    __syncthreads();
    float rn = 1.0f / (sqrtf(ss2[0][l] + ss2[1][l]) + 1e-7f);
    #pragma unroll
    for (int i = 0; i < 32; i++)
        y[((size_t)(b * 64 + half * 32 + i)) * N_ + n] = v[i] * rn;
}

// ---------------- K4: KV partials + fused V-row sum partials -----------------
__global__ __launch_bounds__(256) void kv_kernel() {
    int chunk = blockIdx.x, b = blockIdx.y;
    __shared__ float Ks[64][65];
    __shared__ float Vs[64][65];
    __shared__ float vps[64][4];
    int tid = threadIdx.x;
    int ty = tid >> 4, tx = tid & 15;
    int cc = tid & 63, q4 = tid >> 6;
    float acc[4][4] = {};
    float vp = 0.f;

    for (int t = 0; t < 2; t++) {
        int n0 = chunk * 128 + t * 64;
        #pragma unroll
        for (int i = 0; i < 16; i++) {
            int idx = tid + i * 256;
            int c = idx >> 6, nn = idx & 63;
            Ks[c][nn] = g_yk[((size_t)(b * 64 + c)) * N_ + n0 + nn];
            Vs[c][nn] = g_yv[((size_t)(b * 64 + c)) * N_ + n0 + nn];
        }
        __syncthreads();
        #pragma unroll 8
        for (int n = 0; n < 64; n++) {
            float kv[4], vv[4];
            #pragma unroll
            for (int j = 0; j < 4; j++) kv[j] = Ks[ty + j * 16][n];
            #pragma unroll
            for (int j = 0; j < 4; j++) vv[j] = Vs[tx + j * 16][n];
            #pragma unroll
            for (int j = 0; j < 4; j++)
                #pragma unroll
                for (int i = 0; i < 4; i++)
                    acc[j][i] += kv[j] * vv[i];
        }
        #pragma unroll
        for (int i = 0; i < 16; i++) vp += Vs[cc][q4 * 16 + i];
        __syncthreads();
    }
    #pragma unroll
    for (int j = 0; j < 4; j++)
        #pragma unroll
        for (int i = 0; i < 4; i++)
            g_kvpart[(((size_t)chunk * B_ + b) * 64 + ty + j * 16) * 64 + tx + i * 16] = acc[j][i];

    vps[cc][q4] = vp;
    __syncthreads();
    if (tid < 64)
        g_vsumpart[((size_t)chunk * B_ + b) * 64 + tid] =
            vps[tid][0] + vps[tid][1] + vps[tid][2] + vps[tid][3];
}

// ---------------- K5: per-batch M = KV @ Ww^T, obias = vsum@Ww^T + bw --------
__global__ __launch_bounds__(256) void m_kernel(
    const float* __restrict__ Ww, const float* __restrict__ bw)
{
    int b = blockIdx.x;
    __shared__ float KVs[64][64];
    __shared__ float WwT[64][128];
    __shared__ float vs_s[64];
    int tid = threadIdx.x;

    if (tid < 64) {
        float S = 0.f;
        #pragma unroll
        for (int c2 = 0; c2 < KVCHUNKS; c2++)
            S += g_vsumpart[((size_t)c2 * B_ + b) * 64 + tid];
        vs_s[tid] = S;
    }
    for (int e = tid; e < 4096; e += 256) {
        float s = 0.f;
        #pragma unroll
        for (int c2 = 0; c2 < KVCHUNKS; c2++)
            s += g_kvpart[((size_t)c2 * B_ + b) * 4096 + e];
        KVs[e >> 6][e & 63] = s;
    }
    for (int e = tid; e < 8192; e += 256) {
        int cv = e >> 7, co = e & 127;
        WwT[cv][co] = Ww[co * CV + cv];
    }
    __syncthreads();

    int co = tid & 127;
    for (int ck = (tid >> 7); ck < 64; ck += 2) {
        float s = 0.f;
        #pragma unroll 8
        for (int cv = 0; cv < 64; cv++) s += KVs[ck][cv] * WwT[cv][co];
        g_M[((size_t)b * 64 + ck) * CO + co] = s;
    }
    if (tid < 128) {
        float s = bw[tid];
        #pragma unroll 8
        for (int cv = 0; cv < 64; cv++) s += vs_s[cv] * WwT[cv][tid];
        g_obias[b * CO + tid] = s;
    }
}

// ---------------- K6: out = qnorm^T @ M + obias ------------------------------
__global__ __launch_bounds__(256) void out_kernel(float* __restrict__ out) {
    int b = blockIdx.y, n0 = blockIdx.x * 64;
    int tid = threadIdx.x;
    int ty = tid >> 4, tx = tid & 15;
    __shared__ float Ms[64][128];
    __shared__ float Qs[64][64];

    for (int e = tid; e < 8192; e += 256)
        Ms[e >> 7][e & 127] = g_M[(size_t)b * 8192 + e];
    for (int e = tid; e < 4096; e += 256)
        Qs[e >> 6][e & 63] = g_yq[((size_t)(b * 64 + (e >> 6))) * N_ + n0 + (e & 63)];
    __syncthreads();

    float acc[8][4] = {};
    #pragma unroll 8
    for (int ck = 0; ck < 64; ck++) {
        float4 a0 = *(const float4*)&Ms[ck][ty * 8];
        float4 a1 = *(const float4*)&Ms[ck][ty * 8 + 4];
        float4 q  = *(const float4*)&Qs[ck][tx * 4];
        acc[0][0] += a0.x * q.x; acc[0][1] += a0.x * q.y; acc[0][2] += a0.x * q.z; acc[0][3] += a0.x * q.w;
        acc[1][0] += a0.y * q.x; acc[1][1] += a0.y * q.y; acc[1][2] += a0.y * q.z; acc[1][3] += a0.y * q.w;
        acc[2][0] += a0.z * q.x; acc[2][1] += a0.z * q.y; acc[2][2] += a0.z * q.z; acc[2][3] += a0.z * q.w;
        acc[3][0] += a0.w * q.x; acc[3][1] += a0.w * q.y; acc[3][2] += a0.w * q.z; acc[3][3] += a0.w * q.w;
        acc[4][0] += a1.x * q.x; acc[4][1] += a1.x * q.y; acc[4][2] += a1.x * q.z; acc[4][3] += a1.x * q.w;
        acc[5][0] += a1.y * q.x; acc[5][1] += a1.y * q.y; acc[5][2] += a1.y * q.z; acc[5][3] += a1.y * q.w;
        acc[6][0] += a1.z * q.x; acc[6][1] += a1.z * q.y; acc[6][2] += a1.z * q.z; acc[6][3] += a1.z * q.w;
        acc[7][0] += a1.w * q.x; acc[7][1] += a1.w * q.y; acc[7][2] += a1.w * q.z; acc[7][3] += a1.w * q.w;
    }
    #pragma unroll
    for (int j = 0; j < 8; j++) {
        int co = ty * 8 + j;
        float ob = g_obias[b * CO + co];
        float4 o = make_float4(acc[j][0] + ob, acc[j][1] + ob, acc[j][2] + ob, acc[j][3] + ob);
        *(float4*)&out[((size_t)(b * CO + co)) * N_ + n0 + tx * 4] = o;
    }
}

// ---------------- launch ----------------
extern "C" void kernel_launch(void* const* d_in, const int* in_sizes, int n_in,
                              void* d_out, int out_size) {
    const float* q     = (const float*)d_in[0];
    const float* k     = (const float*)d_in[1];
    const float* v     = (const float*)d_in[2];
    const float* Wk    = (const float*)d_in[3];
    const float* bk    = (const float*)d_in[4];
    const float* gamma = (const float*)d_in[5];
    const float* beta  = (const float*)d_in[6];
    const float* Wv    = (const float*)d_in[7];
    const float* bv    = (const float*)d_in[8];
    const float* Ww    = (const float*)d_in[9];
    const float* bw    = (const float*)d_in[10];
    float* out = (float*)d_out;

    conv_mma_kernel<<<dim3(64, B_, 3), 256>>>(q, k, v, Wk, Wv, bk, bv);
    bn_stats_kernel<<<128, 256>>>(gamma, beta);
    norm_kernel<<<512, 256>>>();
    kv_kernel<<<dim3(KVCHUNKS, B_), 256>>>();
    m_kernel<<<B_, 256>>>(Ww, bw);
    out_kernel<<<dim3(64, B_), 256>>>(out);
}

// round 9
// speedup vs baseline: 2.1034x; 1.2068x over previous
#include <cuda_runtime.h>
#include <cuda_bf16.h>
#include <math.h>

#define B_   8
#define CIN  128
#define CK   64
#define CV   64
#define CO   128
#define N_   4096
#define KVCHUNKS 32

// ---------------- scratch ----------------
__device__ float g_yq[B_ * CK * N_];
__device__ float g_yk[B_ * CK * N_];
__device__ float g_yv[B_ * CV * N_];
__device__ float g_scale[2 * CK];
__device__ float g_shift[2 * CK];
__device__ float g_vsumpart[KVCHUNKS * B_ * CV];
__device__ float g_kvpart[KVCHUNKS * B_ * CK * CV];
__device__ float g_M[B_ * CO * CK];      // TRANSPOSED: [b][co][ck]
__device__ float g_obias[B_ * CO];

// ---------------- mma / ldmatrix helpers ----------------
__device__ __forceinline__ unsigned su32(const void* p) {
    return (unsigned)__cvta_generic_to_shared(p);
}
#define LDSM_X4(r, addr) \
    asm volatile("ldmatrix.sync.aligned.m8n8.x4.shared.b16 {%0,%1,%2,%3}, [%4];" \
        : "=r"((r)[0]), "=r"((r)[1]), "=r"((r)[2]), "=r"((r)[3]) : "r"(addr))
#define LDSM_X4T(r, addr) \
    asm volatile("ldmatrix.sync.aligned.m8n8.x4.trans.shared.b16 {%0,%1,%2,%3}, [%4];" \
        : "=r"((r)[0]), "=r"((r)[1]), "=r"((r)[2]), "=r"((r)[3]) : "r"(addr))
#define MMA_BF16(d, a, b0, b1) \
    asm volatile("mma.sync.aligned.m16n8k16.row.col.f32.bf16.bf16.f32 " \
        "{%0,%1,%2,%3}, {%4,%5,%6,%7}, {%8,%9}, {%0,%1,%2,%3};" \
        : "+f"((d)[0]), "+f"((d)[1]), "+f"((d)[2]), "+f"((d)[3]) \
        : "r"((a)[0]), "r"((a)[1]), "r"((a)[2]), "r"((a)[3]), "r"(b0), "r"(b1))

__device__ __forceinline__ unsigned packbf(__nv_bfloat16 lo, __nv_bfloat16 hi) {
    return ((unsigned)__bfloat16_as_ushort(hi) << 16) | __bfloat16_as_ushort(lo);
}
__device__ __forceinline__ void split4(float4 f, uint2 &hi, uint2 &lo) {
    __nv_bfloat16 hx = __float2bfloat16(f.x), hy = __float2bfloat16(f.y);
    __nv_bfloat16 hz = __float2bfloat16(f.z), hw = __float2bfloat16(f.w);
    __nv_bfloat16 lx = __float2bfloat16(f.x - __bfloat162float(hx));
    __nv_bfloat16 ly = __float2bfloat16(f.y - __bfloat162float(hy));
    __nv_bfloat16 lz = __float2bfloat16(f.z - __bfloat162float(hz));
    __nv_bfloat16 lw = __float2bfloat16(f.w - __bfloat162float(hw));
    hi.x = packbf(hx, hy); hi.y = packbf(hz, hw);
    lo.x = packbf(lx, ly); lo.y = packbf(lz, lw);
}

#define ASTR 72
#define BSTR 72

// ---------------- K1: 1x1 conv via bf16-split MMA (R8, unchanged) -----------
__global__ __launch_bounds__(256) void conv_mma_kernel(
    const float* __restrict__ xq, const float* __restrict__ xk,
    const float* __restrict__ xv,
    const float* __restrict__ Wk, const float* __restrict__ Wv,
    const float* __restrict__ bk, const float* __restrict__ bv)
{
    int which = blockIdx.z;
    const float* x    = (which == 0) ? xq : (which == 1) ? xk : xv;
    const float* W    = (which == 2) ? Wv : Wk;
    const float* bias = (which == 2) ? bv : bk;
    float* y          = (which == 0) ? g_yq : (which == 1) ? g_yk : g_yv;

    int bb = blockIdx.y;
    int n0 = blockIdx.x * 64;
    int tid = threadIdx.x;
    int lane = tid & 31, w = tid >> 5;
    int ct = (w & 3) * 16;
    int ng = (w >> 2) * 32;

    __shared__ __align__(16) __nv_bfloat16 Ah[64 * ASTR];
    __shared__ __align__(16) __nv_bfloat16 Al[64 * ASTR];
    __shared__ __align__(16) __nv_bfloat16 Bh[64 * BSTR];
    __shared__ __align__(16) __nv_bfloat16 Bl[64 * BSTR];

    int q = lane >> 3, rr = lane & 7;
    unsigned aOffH, aOffL, bOffH0, bOffL0, bOffH1, bOffL1;
    {
        int arow = ct + (q & 1) * 8 + rr;
        int acol = (q >> 1) * 8;
        aOffH = su32(Ah) + arow * (ASTR * 2) + acol * 2;
        aOffL = su32(Al) + arow * (ASTR * 2) + acol * 2;
        int brow = (q & 1) * 8 + rr;
        int bcol0 = ng + (q >> 1) * 8;
        int bcol1 = ng + 16 + (q >> 1) * 8;
        bOffH0 = su32(Bh) + brow * (BSTR * 2) + bcol0 * 2;
        bOffL0 = su32(Bl) + brow * (BSTR * 2) + bcol0 * 2;
        bOffH1 = su32(Bh) + brow * (BSTR * 2) + bcol1 * 2;
        bOffL1 = su32(Bl) + brow * (BSTR * 2) + bcol1 * 2;
    }

    float acc[4][4] = {};

    for (int s = 0; s < 2; s++) {
        #pragma unroll
        for (int i = 0; i < 4; i++) {
            int e = tid + i * 256;
            int co = e >> 4, ci4 = (e & 15) * 4;
            float4 f = *(const float4*)&W[co * CIN + s * 64 + ci4];
            uint2 hi, lo; split4(f, hi, lo);
            *(uint2*)&Ah[co * ASTR + ci4] = hi;
            *(uint2*)&Al[co * ASTR + ci4] = lo;
        }
        #pragma unroll
        for (int i = 0; i < 4; i++) {
            int e = tid + i * 256;
            int ci = e >> 4, nn4 = (e & 15) * 4;
            float4 f = *(const float4*)&x[((size_t)(bb * CIN + s * 64 + ci)) * N_ + n0 + nn4];
            uint2 hi, lo; split4(f, hi, lo);
            *(uint2*)&Bh[ci * BSTR + nn4] = hi;
            *(uint2*)&Bl[ci * BSTR + nn4] = lo;
        }
        __syncthreads();

        #pragma unroll
        for (int ks = 0; ks < 4; ks++) {
            unsigned aStep = ks * 32;
            unsigned bStep = ks * 16 * (BSTR * 2);
            unsigned ah[4], al[4], bh[4], bl[4], bh2[4], bl2[4];
            LDSM_X4(ah, aOffH + aStep);
            LDSM_X4(al, aOffL + aStep);
            LDSM_X4T(bh, bOffH0 + bStep);
            LDSM_X4T(bl, bOffL0 + bStep);
            LDSM_X4T(bh2, bOffH1 + bStep);
            LDSM_X4T(bl2, bOffL1 + bStep);
            MMA_BF16(acc[0], ah, bh[0], bh[1]);
            MMA_BF16(acc[0], ah, bl[0], bl[1]);
            MMA_BF16(acc[0], al, bh[0], bh[1]);
            MMA_BF16(acc[1], ah, bh[2], bh[3]);
            MMA_BF16(acc[1], ah, bl[2], bl[3]);
            MMA_BF16(acc[1], al, bh[2], bh[3]);
            MMA_BF16(acc[2], ah, bh2[0], bh2[1]);
            MMA_BF16(acc[2], ah, bl2[0], bl2[1]);
            MMA_BF16(acc[2], al, bh2[0], bh2[1]);
            MMA_BF16(acc[3], ah, bh2[2], bh2[3]);
            MMA_BF16(acc[3], ah, bl2[2], bl2[3]);
            MMA_BF16(acc[3], al, bh2[2], bh2[3]);
        }
        __syncthreads();
    }

    int r4 = lane >> 2, c2 = (lane & 3) * 2;
    int row0 = ct + r4, row1 = ct + r4 + 8;
    float b0v = bias[row0], b1v = bias[row1];
    #pragma unroll
    for (int t = 0; t < 4; t++) {
        int col = n0 + ng + t * 8 + c2;
        *(float2*)&y[((size_t)(bb * 64 + row0)) * N_ + col] =
            make_float2(acc[t][0] + b0v, acc[t][1] + b0v);
        *(float2*)&y[((size_t)(bb * 64 + row1)) * N_ + col] =
            make_float2(acc[t][2] + b1v, acc[t][3] + b1v);
    }
}

// ---------------- K2: BN batch stats ----------------
__global__ __launch_bounds__(256) void bn_stats_kernel(
    const float* __restrict__ gamma, const float* __restrict__ beta)
{
    int c = blockIdx.x & 63;
    int which = blockIdx.x >> 6;
    const float* y = which ? g_yk : g_yq;
    int tid = threadIdx.x;

    float s = 0.f, ss = 0.f;
    #pragma unroll
    for (int b = 0; b < B_; b++) {
        const float4* row = (const float4*)(y + ((size_t)(b * 64 + c)) * N_);
        #pragma unroll
        for (int i = 0; i < 4; i++) {
            float4 f = row[tid + i * 256];
            s  += f.x + f.y + f.z + f.w;
            ss += f.x * f.x + f.y * f.y + f.z * f.z + f.w * f.w;
        }
    }
    #pragma unroll
    for (int o = 16; o; o >>= 1) {
        s  += __shfl_down_sync(0xffffffffu, s, o);
        ss += __shfl_down_sync(0xffffffffu, ss, o);
    }
    __shared__ float rs[8], rss[8];
    int wid = tid >> 5, lane = tid & 31;
    if (lane == 0) { rs[wid] = s; rss[wid] = ss; }
    __syncthreads();
    if (tid == 0) {
        float S = 0.f, SS = 0.f;
        #pragma unroll
        for (int i = 0; i < 8; i++) { S += rs[i]; SS += rss[i]; }
        const float inv = 1.0f / 32768.0f;
        float mean = S * inv;
        float var  = SS * inv - mean * mean;
        float sc = gamma[c] * rsqrtf(var + 1e-5f);
        g_scale[blockIdx.x] = sc;
        g_shift[blockIdx.x] = beta[c] - mean * sc;
    }
}

// ---------------- K3: apply BN + L2-normalize ----------------
__global__ __launch_bounds__(256) void norm_kernel() {
    int colblk = blockIdx.x;
    int which = colblk >> 8;
    int r = colblk & 255;
    int b = r >> 5;
    int n0 = (r & 31) * 128;
    float* y = which ? g_yk : g_yq;
    int tid = threadIdx.x;
    int half = tid >> 7;
    int l = tid & 127;
    int n = n0 + l;

    __shared__ float scs[64], shs[64], ss2[2][128];
    if (tid < 64) {
        scs[tid] = g_scale[which * 64 + tid];
        shs[tid] = g_shift[which * 64 + tid];
    }
    __syncthreads();

    float v[32];
    float ss = 0.f;
    #pragma unroll
    for (int i = 0; i < 32; i++) {
        int c = half * 32 + i;
        float t = y[((size_t)(b * 64 + c)) * N_ + n] * scs[c] + shs[c];
        v[i] = t; ss += t * t;
    }
    ss2[half][l] = ss;
    __syncthreads();
    float rn = 1.0f / (sqrtf(ss2[0][l] + ss2[1][l]) + 1e-7f);
    #pragma unroll
    for (int i = 0; i < 32; i++)
        y[((size_t)(b * 64 + half * 32 + i)) * N_ + n] = v[i] * rn;
}

// ---------------- K4: KV via bf16-split MMA + fused vsum partials ------------
// grid (KVCHUNKS, B_), 256 threads. A=K[ck][n], B=V[cv][n] (plain LDSM, [N][K]).
__global__ __launch_bounds__(256) void kv_mma_kernel() {
    int chunk = blockIdx.x, b = blockIdx.y;
    int tid = threadIdx.x;
    int lane = tid & 31, w = tid >> 5;
    int ct = (w & 3) * 16;            // ck tile base
    int cg = (w >> 2) * 32;           // cv half base

    __shared__ __align__(16) __nv_bfloat16 Kh[64 * ASTR];
    __shared__ __align__(16) __nv_bfloat16 Kl[64 * ASTR];
    __shared__ __align__(16) __nv_bfloat16 Vh[64 * ASTR];
    __shared__ __align__(16) __nv_bfloat16 Vl[64 * ASTR];
    __shared__ float vps[64][4];

    int q = lane >> 3, rr = lane & 7;
    unsigned aH, aL, bH0, bL0, bH1, bL1;
    {
        int arow = ct + (q & 1) * 8 + rr;
        int acol = (q >> 1) * 8;
        aH = su32(Kh) + arow * (ASTR * 2) + acol * 2;
        aL = su32(Kl) + arow * (ASTR * 2) + acol * 2;
        // plain LDSM on [cv][k]: q0:(cv,k0) q1:(cv,k8) q2:(cv+8,k0) q3:(cv+8,k8)
        int brow = cg + (q >> 1) * 8 + rr;
        int bcol = (q & 1) * 8;
        bH0 = su32(Vh) + brow * (ASTR * 2) + bcol * 2;
        bL0 = su32(Vl) + brow * (ASTR * 2) + bcol * 2;
        bH1 = bH0 + 16 * (ASTR * 2);   // cv +16
        bL1 = bL0 + 16 * (ASTR * 2);
    }

    int cc = tid & 63, q4 = tid >> 6;
    float acc[4][4] = {};
    float vp = 0.f;

    for (int t = 0; t < 2; t++) {
        int n0 = chunk * 128 + t * 64;
        #pragma unroll
        for (int i = 0; i < 4; i++) {
            int e = tid + i * 256;
            int row = e >> 4, nn4 = (e & 15) * 4;
            float4 fk = *(const float4*)&g_yk[((size_t)(b * 64 + row)) * N_ + n0 + nn4];
            float4 fv = *(const float4*)&g_yv[((size_t)(b * 64 + row)) * N_ + n0 + nn4];
            uint2 hi, lo;
            split4(fk, hi, lo);
            *(uint2*)&Kh[row * ASTR + nn4] = hi;
            *(uint2*)&Kl[row * ASTR + nn4] = lo;
            split4(fv, hi, lo);
            *(uint2*)&Vh[row * ASTR + nn4] = hi;
            *(uint2*)&Vl[row * ASTR + nn4] = lo;
        }
        __syncthreads();

        #pragma unroll
        for (int ks = 0; ks < 4; ks++) {
            unsigned step = ks * 32;       // 16 bf16 along k(n)
            unsigned ah[4], al[4], bh[4], bl[4], bh2[4], bl2[4];
            LDSM_X4(ah, aH + step);
            LDSM_X4(al, aL + step);
            LDSM_X4(bh, bH0 + step);
            LDSM_X4(bl, bL0 + step);
            LDSM_X4(bh2, bH1 + step);
            LDSM_X4(bl2, bL1 + step);
            MMA_BF16(acc[0], ah, bh[0], bh[1]);
            MMA_BF16(acc[0], ah, bl[0], bl[1]);
            MMA_BF16(acc[0], al, bh[0], bh[1]);
            MMA_BF16(acc[1], ah, bh[2], bh[3]);
            MMA_BF16(acc[1], ah, bl[2], bl[3]);
            MMA_BF16(acc[1], al, bh[2], bh[3]);
            MMA_BF16(acc[2], ah, bh2[0], bh2[1]);
            MMA_BF16(acc[2], ah, bl2[0], bl2[1]);
            MMA_BF16(acc[2], al, bh2[0], bh2[1]);
            MMA_BF16(acc[3], ah, bh2[2], bh2[3]);
            MMA_BF16(acc[3], ah, bl2[2], bl2[3]);
            MMA_BF16(acc[3], al, bh2[2], bh2[3]);
        }
        // fused V row sums (hi+lo) from smem bf16
        #pragma unroll
        for (int i = 0; i < 16; i++) {
            int idx = cc * ASTR + q4 * 16 + i;
            vp += __bfloat162float(Vh[idx]) + __bfloat162float(Vl[idx]);
        }
        __syncthreads();
    }

    // epilogue: D[ck][cv] fragments
    int r4 = lane >> 2, c2 = (lane & 3) * 2;
    int row0 = ct + r4, row1 = ct + r4 + 8;
    float* base = &g_kvpart[(((size_t)chunk * B_ + b)) * 4096];
    #pragma unroll
    for (int t = 0; t < 4; t++) {
        int col = cg + t * 8 + c2;
        *(float2*)&base[row0 * 64 + col] = make_float2(acc[t][0], acc[t][1]);
        *(float2*)&base[row1 * 64 + col] = make_float2(acc[t][2], acc[t][3]);
    }

    vps[cc][q4] = vp;
    __syncthreads();
    if (tid < 64)
        g_vsumpart[((size_t)chunk * B_ + b) * 64 + tid] =
            vps[tid][0] + vps[tid][1] + vps[tid][2] + vps[tid][3];
}

// ---------------- K5: M^T = (KV @ Ww^T)^T stored [co][ck]; obias -------------
__global__ __launch_bounds__(256) void m_kernel(
    const float* __restrict__ Ww, const float* __restrict__ bw)
{
    int b = blockIdx.x;
    __shared__ float KVs[64][64];
    __shared__ float WwT[64][128];
    __shared__ float vs_s[64];
    int tid = threadIdx.x;

    if (tid < 64) {
        float S = 0.f;
        #pragma unroll
        for (int c2 = 0; c2 < KVCHUNKS; c2++)
            S += g_vsumpart[((size_t)c2 * B_ + b) * 64 + tid];
        vs_s[tid] = S;
    }
    for (int e = tid; e < 4096; e += 256) {
        float s = 0.f;
        #pragma unroll
        for (int c2 = 0; c2 < KVCHUNKS; c2++)
            s += g_kvpart[((size_t)c2 * B_ + b) * 4096 + e];
        KVs[e >> 6][e & 63] = s;
    }
    for (int e = tid; e < 8192; e += 256) {
        int cv = e >> 7, co = e & 127;
        WwT[cv][co] = Ww[co * CV + cv];
    }
    __syncthreads();

    int co = tid & 127;
    for (int ck = (tid >> 7); ck < 64; ck += 2) {
        float s = 0.f;
        #pragma unroll 8
        for (int cv = 0; cv < 64; cv++) s += KVs[ck][cv] * WwT[cv][co];
        g_M[((size_t)b * 128 + co) * 64 + ck] = s;    // transposed store
    }
    if (tid < 128) {
        float s = bw[tid];
        #pragma unroll 8
        for (int cv = 0; cv < 64; cv++) s += vs_s[cv] * WwT[cv][tid];
        g_obias[b * CO + tid] = s;
    }
}

// ---------------- K6: out via bf16-split MMA ---------------------------------
// grid (64, B_, 2), 256 threads. A=M^T[co][ck], B=q_norm[ck][n] (trans LDSM).
__global__ __launch_bounds__(256) void out_mma_kernel(float* __restrict__ out) {
    int b = blockIdx.y, n0 = blockIdx.x * 64, ch = blockIdx.z;
    int co0 = ch * 64;
    int tid = threadIdx.x;
    int lane = tid & 31, w = tid >> 5;
    int ct = (w & 3) * 16;            // co tile base (local)
    int ng = (w >> 2) * 32;           // n half base

    __shared__ __align__(16) __nv_bfloat16 Ah[64 * ASTR];
    __shared__ __align__(16) __nv_bfloat16 Al[64 * ASTR];
    __shared__ __align__(16) __nv_bfloat16 Bh[64 * BSTR];
    __shared__ __align__(16) __nv_bfloat16 Bl[64 * BSTR];

    int q = lane >> 3, rr = lane & 7;
    unsigned aOffH, aOffL, bOffH0, bOffL0, bOffH1, bOffL1;
    {
        int arow = ct + (q & 1) * 8 + rr;
        int acol = (q >> 1) * 8;
        aOffH = su32(Ah) + arow * (ASTR * 2) + acol * 2;
        aOffL = su32(Al) + arow * (ASTR * 2) + acol * 2;
        int brow = (q & 1) * 8 + rr;
        int bcol0 = ng + (q >> 1) * 8;
        int bcol1 = ng + 16 + (q >> 1) * 8;
        bOffH0 = su32(Bh) + brow * (BSTR * 2) + bcol0 * 2;
        bOffL0 = su32(Bl) + brow * (BSTR * 2) + bcol0 * 2;
        bOffH1 = su32(Bh) + brow * (BSTR * 2) + bcol1 * 2;
        bOffL1 = su32(Bl) + brow * (BSTR * 2) + bcol1 * 2;
    }

    // stage A: M^T rows co0..co0+63 x 64 ck
    #pragma unroll
    for (int i = 0; i < 4; i++) {
        int e = tid + i * 256;
        int row = e >> 4, ck4 = (e & 15) * 4;
        float4 f = *(const float4*)&g_M[((size_t)b * 128 + co0 + row) * 64 + ck4];
        uint2 hi, lo; split4(f, hi, lo);
        *(uint2*)&Ah[row * ASTR + ck4] = hi;
        *(uint2*)&Al[row * ASTR + ck4] = lo;
    }
    // stage B: q_norm [ck][n]
    #pragma unroll
    for (int i = 0; i < 4; i++) {
        int e = tid + i * 256;
        int ck = e >> 4, nn4 = (e & 15) * 4;
        float4 f = *(const float4*)&g_yq[((size_t)(b * 64 + ck)) * N_ + n0 + nn4];
        uint2 hi, lo; split4(f, hi, lo);
        *(uint2*)&Bh[ck * BSTR + nn4] = hi;
        *(uint2*)&Bl[ck * BSTR + nn4] = lo;
    }
    __syncthreads();

    float acc[4][4] = {};
    #pragma unroll
    for (int ks = 0; ks < 4; ks++) {
        unsigned aStep = ks * 32;
        unsigned bStep = ks * 16 * (BSTR * 2);
        unsigned ah[4], al[4], bh[4], bl[4], bh2[4], bl2[4];
        LDSM_X4(ah, aOffH + aStep);
        LDSM_X4(al, aOffL + aStep);
        LDSM_X4T(bh, bOffH0 + bStep);
        LDSM_X4T(bl, bOffL0 + bStep);
        LDSM_X4T(bh2, bOffH1 + bStep);
        LDSM_X4T(bl2, bOffL1 + bStep);
        MMA_BF16(acc[0], ah, bh[0], bh[1]);
        MMA_BF16(acc[0], ah, bl[0], bl[1]);
        MMA_BF16(acc[0], al, bh[0], bh[1]);
        MMA_BF16(acc[1], ah, bh[2], bh[3]);
        MMA_BF16(acc[1], ah, bl[2], bl[3]);
        MMA_BF16(acc[1], al, bh[2], bh[3]);
        MMA_BF16(acc[2], ah, bh2[0], bh2[1]);
        MMA_BF16(acc[2], ah, bl2[0], bl2[1]);
        MMA_BF16(acc[2], al, bh2[0], bh2[1]);
        MMA_BF16(acc[3], ah, bh2[2], bh2[3]);
        MMA_BF16(acc[3], ah, bl2[2], bl2[3]);
        MMA_BF16(acc[3], al, bh2[2], bh2[3]);
    }

    int r4 = lane >> 2, c2 = (lane & 3) * 2;
    int row0 = co0 + ct + r4, row1 = row0 + 8;
    float b0v = g_obias[b * CO + row0], b1v = g_obias[b * CO + row1];
    #pragma unroll
    for (int t = 0; t < 4; t++) {
        int col = n0 + ng + t * 8 + c2;
        *(float2*)&out[((size_t)(b * CO + row0)) * N_ + col] =
            make_float2(acc[t][0] + b0v, acc[t][1] + b0v);
        *(float2*)&out[((size_t)(b * CO + row1)) * N_ + col] =
            make_float2(acc[t][2] + b1v, acc[t][3] + b1v);
    }
}

// ---------------- launch ----------------
extern "C" void kernel_launch(void* const* d_in, const int* in_sizes, int n_in,
                              void* d_out, int out_size) {
    const float* q     = (const float*)d_in[0];
    const float* k     = (const float*)d_in[1];
    const float* v     = (const float*)d_in[2];
    const float* Wk    = (const float*)d_in[3];
    const float* bk    = (const float*)d_in[4];
    const float* gamma = (const float*)d_in[5];
    const float* beta  = (const float*)d_in[6];
    const float* Wv    = (const float*)d_in[7];
    const float* bv    = (const float*)d_in[8];
    const float* Ww    = (const float*)d_in[9];
    const float* bw    = (const float*)d_in[10];
    float* out = (float*)d_out;

    conv_mma_kernel<<<dim3(64, B_, 3), 256>>>(q, k, v, Wk, Wv, bk, bv);
    bn_stats_kernel<<<128, 256>>>(gamma, beta);
    norm_kernel<<<512, 256>>>();
    kv_mma_kernel<<<dim3(KVCHUNKS, B_), 256>>>();
    m_kernel<<<B_, 256>>>(Ww, bw);
    out_mma_kernel<<<dim3(64, B_, 2), 256>>>(out);
}